// round 8
// baseline (speedup 1.0000x reference)
#include <cuda_runtime.h>
#include <cuda_bf16.h>
#include <math.h>
#include <stdint.h>

#define N2 4096
#define NB 2048
#define DK 128
#define TAU_INV 10.0f
#define TM 128
#define TN 128
#define NT 32               // number of 128-row tiles
#define NPAIRS (NT * (NT + 1) / 2)   // 528
#define LDA 136             // bf16 elements per smem row (128 + 8 pad)

// ---------------- device scratch ----------------
__device__ uint4 g_Q4[(N2 * DK) / 8];    // normalized rows, bf16, 16B-aligned
__device__ int   g_lbl[N2];
__device__ float g_Zp[N2 * NT];          // [row][slot] contiguous per row
__device__ float g_Sp[N2 * NT];
__device__ float g_part[16];
__device__ int   g_ctr;

// ---------------- kernel 1: normalize (4 rows/warp, MLP=4) -----------------
__global__ void normalize_kernel(const float* __restrict__ zi,
                                 const float* __restrict__ zj,
                                 const long long* __restrict__ y) {
    if (blockIdx.x == 0 && threadIdx.x == 0) g_ctr = 0;   // replay-safe reset
    int wid  = threadIdx.x >> 5, lane = threadIdx.x & 31;
    int row0 = (blockIdx.x * 8 + wid) * 4;

    float4 v[4];
#pragma unroll
    for (int r = 0; r < 4; r++) {
        int row = row0 + r;
        const float* src = (row < NB) ? (zi + (size_t)row * DK)
                                      : (zj + (size_t)(row - NB) * DK);
        v[r] = ((const float4*)src)[lane];
    }
    float ss[4];
#pragma unroll
    for (int r = 0; r < 4; r++)
        ss[r] = v[r].x * v[r].x + v[r].y * v[r].y
              + v[r].z * v[r].z + v[r].w * v[r].w;
#pragma unroll
    for (int m = 16; m; m >>= 1)
#pragma unroll
        for (int r = 0; r < 4; r++)
            ss[r] += __shfl_xor_sync(0xffffffffu, ss[r], m);

    uint32_t* q32 = (uint32_t*)g_Q4;
#pragma unroll
    for (int r = 0; r < 4; r++) {
        float inv = rsqrtf(fmaxf(ss[r], 1e-30f));
        uint32_t p01, p23;
        asm("cvt.rn.bf16x2.f32 %0, %1, %2;" : "=r"(p01)
            : "f"(v[r].y * inv), "f"(v[r].x * inv));
        asm("cvt.rn.bf16x2.f32 %0, %1, %2;" : "=r"(p23)
            : "f"(v[r].w * inv), "f"(v[r].z * inv));
        q32[(row0 + r) * 64 + 2 * lane + 0] = p01;
        q32[(row0 + r) * 64 + 2 * lane + 1] = p23;
    }
    if (lane < 4) g_lbl[row0 + lane] = (int)y[(row0 + lane) & (NB - 1)];
}

// ---------------- kernel 2: symmetric bf16 HMMA sim + fused stats ----------
#define SM_A   0
#define SM_B   (TM * LDA * 2)                 // 34816
#define SM_LI  (SM_B + TN * LDA * 2)          // 69632
#define SM_LJ  (SM_LI + 512)                  // 70144
#define SM_ZR  (SM_LJ + 512)                  // 70656  float[4][128]
#define SM_SR  (SM_ZR + 2048)                 // 72704  float[4][128]
#define SM_CZ  (SM_SR + 2048)                 // 74752  float[2][128]
#define SM_CS  (SM_CZ + 1024)                 // 75776  float[2][128]
#define SM_TOTAL (SM_CS + 1024)               // 76800

__global__ void __launch_bounds__(256, 2) sim_kernel() {
    extern __shared__ char smem[];
    __nv_bfloat16* sA = (__nv_bfloat16*)(smem + SM_A);
    __nv_bfloat16* sB = (__nv_bfloat16*)(smem + SM_B);
    int*   li = (int*)(smem + SM_LI);
    int*   lj = (int*)(smem + SM_LJ);
    float* zr = (float*)(smem + SM_ZR);
    float* sr = (float*)(smem + SM_SR);
    float* cz = (float*)(smem + SM_CZ);
    float* cs = (float*)(smem + SM_CS);

    // triangular pair decode: t = J(J+1)/2 + I, 0 <= I <= J < 32
    int t = blockIdx.x;
    int J = (int)((sqrtf(8.0f * t + 1.0f) - 1.0f) * 0.5f);
    while ((J + 1) * (J + 2) / 2 <= t) ++J;
    while (J * (J + 1) / 2 > t) --J;
    int I = t - J * (J + 1) / 2;
    const bool offdiag = (I != J);

    const int tid  = threadIdx.x;
    const int wid  = tid >> 5, lane = tid & 31;
    const int ibase = I * TM, jbase = J * TN;

    // ---- load tiles ----
    {
        int r0 = tid >> 4, ch = tid & 15;
#pragma unroll
        for (int it = 0; it < 8; it++) {
            int r = r0 + it * 16;
            uint4 va = g_Q4[(size_t)(ibase + r) * (DK / 8) + ch];
            *(uint4*)((char*)sA + r * (LDA * 2) + ch * 16) = va;
            uint4 vb = g_Q4[(size_t)(jbase + r) * (DK / 8) + ch];
            *(uint4*)((char*)sB + r * (LDA * 2) + ch * 16) = vb;
        }
    }
    if (tid < TM) li[tid] = g_lbl[ibase + tid];
    else if (tid < TM + TN) lj[tid - TM] = g_lbl[jbase + tid - TM];
    __syncthreads();

    // ---- warp tiling: 2 (m) x 4 (n); warp tile 64x32 ----
    const int wy = wid >> 2, wx = wid & 3;
    const int m0w = wy * 64, n0w = wx * 32;
    const int g = lane >> 2, tq = lane & 3;

    float acc[4][4][4];
#pragma unroll
    for (int mt = 0; mt < 4; mt++)
#pragma unroll
        for (int nt = 0; nt < 4; nt++)
#pragma unroll
            for (int e = 0; e < 4; e++) acc[mt][nt][e] = 0.f;

#pragma unroll
    for (int ks = 0; ks < 8; ks++) {
        const int kk = ks * 16;
        uint32_t Af[4][4];
#pragma unroll
        for (int mt = 0; mt < 4; mt++) {
            const __nv_bfloat16* base = &sA[(m0w + mt * 16 + g) * LDA + kk + 2 * tq];
            Af[mt][0] = *(const uint32_t*)(base);
            Af[mt][1] = *(const uint32_t*)(base + 8 * LDA);
            Af[mt][2] = *(const uint32_t*)(base + 8);
            Af[mt][3] = *(const uint32_t*)(base + 8 * LDA + 8);
        }
        uint32_t Bf[4][2];
#pragma unroll
        for (int nt = 0; nt < 4; nt++) {
            const __nv_bfloat16* base = &sB[(n0w + nt * 8 + g) * LDA + kk + 2 * tq];
            Bf[nt][0] = *(const uint32_t*)(base);
            Bf[nt][1] = *(const uint32_t*)(base + 8);
        }
#pragma unroll
        for (int mt = 0; mt < 4; mt++)
#pragma unroll
            for (int nt = 0; nt < 4; nt++) {
                asm volatile(
                    "mma.sync.aligned.m16n8k16.row.col.f32.bf16.bf16.f32 "
                    "{%0,%1,%2,%3}, {%4,%5,%6,%7}, {%8,%9}, {%0,%1,%2,%3};"
                    : "+f"(acc[mt][nt][0]), "+f"(acc[mt][nt][1]),
                      "+f"(acc[mt][nt][2]), "+f"(acc[mt][nt][3])
                    : "r"(Af[mt][0]), "r"(Af[mt][1]),
                      "r"(Af[mt][2]), "r"(Af[mt][3]),
                      "r"(Bf[nt][0]), "r"(Bf[nt][1]));
            }
    }

    // ---- fused epilogue, specialized on diag/offdiag ----
    if (offdiag) {
        // no diagonal in this tile: unconditional exp; column stats active
        float zc[8], sc[8];
#pragma unroll
        for (int q = 0; q < 8; q++) { zc[q] = 0.f; sc[q] = 0.f; }

#pragma unroll
        for (int mt = 0; mt < 4; mt++) {
            int rl0 = m0w + mt * 16 + g;
            int rl1 = rl0 + 8;
            int l0 = li[rl0], l1 = li[rl1];
            float z0 = 0.f, s0 = 0.f, z1 = 0.f, s1 = 0.f;
#pragma unroll
            for (int nt = 0; nt < 4; nt++) {
                int cb = n0w + nt * 8 + 2 * tq;
#pragma unroll
                for (int e = 0; e < 2; e++) {
                    int col = cb + e, ljv = lj[col];
                    float lg0 = acc[mt][nt][e] * TAU_INV;
                    float lg1 = acc[mt][nt][2 + e] * TAU_INV;
                    float e0 = __expf(lg0);
                    float e1 = __expf(lg1);
                    float m0 = (ljv == l0) ? lg0 : 0.f;
                    float m1 = (ljv == l1) ? lg1 : 0.f;
                    z0 += e0; s0 += m0;
                    z1 += e1; s1 += m1;
                    zc[nt * 2 + e] += e0 + e1;
                    sc[nt * 2 + e] += m0 + m1;
                }
            }
#pragma unroll
            for (int m = 1; m <= 2; m <<= 1) {
                z0 += __shfl_xor_sync(0xffffffffu, z0, m);
                s0 += __shfl_xor_sync(0xffffffffu, s0, m);
                z1 += __shfl_xor_sync(0xffffffffu, z1, m);
                s1 += __shfl_xor_sync(0xffffffffu, s1, m);
            }
            if (tq == 0) {
                zr[wx * 128 + rl0] = z0;  sr[wx * 128 + rl0] = s0;
                zr[wx * 128 + rl1] = z1;  sr[wx * 128 + rl1] = s1;
            }
        }
        // reduce col partials over the 8 g-lanes (same tq share columns)
#pragma unroll
        for (int m = 4; m <= 16; m <<= 1)
#pragma unroll
            for (int q = 0; q < 8; q++) {
                zc[q] += __shfl_xor_sync(0xffffffffu, zc[q], m);
                sc[q] += __shfl_xor_sync(0xffffffffu, sc[q], m);
            }
        if (g == 0) {
#pragma unroll
            for (int nt = 0; nt < 4; nt++)
#pragma unroll
                for (int e = 0; e < 2; e++) {
                    int col = n0w + nt * 8 + 2 * tq + e;
                    cz[wy * 128 + col] = zc[nt * 2 + e];
                    cs[wy * 128 + col] = sc[nt * 2 + e];
                }
        }
    } else {
        // diagonal tile: guard gi != gj, no column stats
#pragma unroll
        for (int mt = 0; mt < 4; mt++) {
            int rl0 = m0w + mt * 16 + g;
            int rl1 = rl0 + 8;
            int gi0 = ibase + rl0, gi1 = ibase + rl1;
            int l0 = li[rl0], l1 = li[rl1];
            float z0 = 0.f, s0 = 0.f, z1 = 0.f, s1 = 0.f;
#pragma unroll
            for (int nt = 0; nt < 4; nt++) {
                int cb = n0w + nt * 8 + 2 * tq;
#pragma unroll
                for (int e = 0; e < 2; e++) {
                    int col = cb + e, gj = jbase + col, ljv = lj[col];
                    float lg0 = acc[mt][nt][e] * TAU_INV;
                    float lg1 = acc[mt][nt][2 + e] * TAU_INV;
                    if (gi0 != gj) {
                        z0 += __expf(lg0);
                        if (ljv == l0) s0 += lg0;
                    }
                    if (gi1 != gj) {
                        z1 += __expf(lg1);
                        if (ljv == l1) s1 += lg1;
                    }
                }
            }
#pragma unroll
            for (int m = 1; m <= 2; m <<= 1) {
                z0 += __shfl_xor_sync(0xffffffffu, z0, m);
                s0 += __shfl_xor_sync(0xffffffffu, s0, m);
                z1 += __shfl_xor_sync(0xffffffffu, z1, m);
                s1 += __shfl_xor_sync(0xffffffffu, s1, m);
            }
            if (tq == 0) {
                zr[wx * 128 + rl0] = z0;  sr[wx * 128 + rl0] = s0;
                zr[wx * 128 + rl1] = z1;  sr[wx * 128 + rl1] = s1;
            }
        }
    }
    __syncthreads();

    if (tid < TM) {
        float Z = 0.f, S = 0.f;
#pragma unroll
        for (int w = 0; w < 4; w++) {
            Z += zr[w * 128 + tid];
            S += sr[w * 128 + tid];
        }
        g_Zp[(ibase + tid) * NT + J] = Z;
        g_Sp[(ibase + tid) * NT + J] = S;
        if (offdiag) {
            float Zc = cz[tid] + cz[128 + tid];
            float Sc = cs[tid] + cs[128 + tid];
            g_Zp[(jbase + tid) * NT + I] = Zc;
            g_Sp[(jbase + tid) * NT + I] = Sc;
        }
    }
}

// ---------------- kernel 3: reduction + finalize (ballot histogram) --------
__global__ void fin_kernel(float* __restrict__ out) {
    __shared__ float red[256];
    __shared__ int hist[16];
    __shared__ int amLast;
    int tid = threadIdx.x, wid = tid >> 5, lane = tid & 31;
    if (tid < 16) hist[tid] = 0;
    __syncthreads();

    // warp-aggregated histogram: lane b accumulates bin b via ballots
    {
        int mycnt = 0;
#pragma unroll
        for (int it = 0; it < 16; it++) {
            int l = g_lbl[it * 256 + wid * 32 + lane];
#pragma unroll
            for (int b = 0; b < 10; b++) {
                unsigned m = __ballot_sync(0xffffffffu, l == b);
                if (lane == b) mycnt += __popc(m);
            }
        }
        if (lane < 10) atomicAdd(&hist[lane], mycnt);
    }
    __syncthreads();

    int i = blockIdx.x * 256 + tid;
    const float4* zp4 = (const float4*)&g_Zp[i * NT];
    const float4* sp4 = (const float4*)&g_Sp[i * NT];
    float Z = 0.f, S = 0.f;
#pragma unroll
    for (int q = 0; q < 8; q++) {
        float4 a = zp4[q], b = sp4[q];
        Z += a.x + a.y + a.z + a.w;
        S += b.x + b.y + b.z + b.w;
    }
    float cnt = (float)(hist[g_lbl[i] & 15] - 1);
    red[tid] = S / cnt - logf(Z);
    __syncthreads();
    for (int s = 128; s; s >>= 1) {
        if (tid < s) red[tid] += red[tid + s];
        __syncthreads();
    }
    if (tid == 0) {
        g_part[blockIdx.x] = red[0];
        __threadfence();
        amLast = (atomicAdd(&g_ctr, 1) == 15);
    }
    __syncthreads();
    if (amLast && tid < 32) {
        float v = (tid < 16) ? g_part[tid] : 0.f;
#pragma unroll
        for (int m = 16; m; m >>= 1) v += __shfl_xor_sync(0xffffffffu, v, m);
        if (tid == 0) out[0] = -v / (float)N2;
    }
}

// ---------------- launch ----------------
extern "C" void kernel_launch(void* const* d_in, const int* in_sizes, int n_in,
                              void* d_out, int out_size) {
    const float*     zi = (const float*)d_in[0];
    const float*     zj = (const float*)d_in[1];
    const long long* y  = (const long long*)d_in[2];
    float* out = (float*)d_out;

    cudaFuncSetAttribute(sim_kernel,
                         cudaFuncAttributeMaxDynamicSharedMemorySize, SM_TOTAL);

    normalize_kernel<<<N2 / 32, 256>>>(zi, zj, y);
    sim_kernel<<<NPAIRS, 256, SM_TOTAL>>>();
    fin_kernel<<<16, 256>>>(out);
}

// round 9
// speedup vs baseline: 1.1616x; 1.1616x over previous
#include <cuda_runtime.h>
#include <cuda_bf16.h>
#include <math.h>
#include <stdint.h>

#define N2 4096
#define NB 2048
#define DK 128
#define TAU_INV 10.0f
#define TM 128
#define TN 128
#define NT 32                        // number of 128-row tiles
#define NPAIRS (NT * (NT + 1) / 2)   // 528
#define LDA 136                      // bf16 elements per smem row (128 + 8 pad)
#define NCTA 296                     // 148 SMs x 2 CTAs/SM (co-resident)

// ---------------- device scratch ----------------
__device__ uint4 g_Q4[(N2 * DK) / 8];    // normalized rows, bf16
__device__ int   g_lbl[N2];
__device__ int   g_hist[16];
__device__ float g_Zp[N2 * NT];          // [row][slot] contiguous per row
__device__ float g_Sp[N2 * NT];
__device__ float g_part[NCTA];
__device__ int   g_bar;                  // monotonic ticket barrier (never reset)

// ---------------- grid barrier: monotonic ticket, replay-safe --------------
__device__ __forceinline__ void grid_barrier() {
    __syncthreads();
    if (threadIdx.x == 0) {
        __threadfence();
        int t = atomicAdd(&g_bar, 1) + 1;
        int target = ((t + NCTA - 1) / NCTA) * NCTA;
        int v;
        do {
            asm volatile("ld.global.acquire.gpu.b32 %0, [%1];"
                         : "=r"(v) : "l"(&g_bar));
        } while (v < target);
    }
    __syncthreads();
}

// ---------------- smem layout ----------------
#define SM_A   0
#define SM_B   (TM * LDA * 2)                 // 34816
#define SM_LI  (SM_B + TN * LDA * 2)          // 69632
#define SM_LJ  (SM_LI + 512)                  // 70144
#define SM_ZR  (SM_LJ + 512)                  // 70656  float[4][128]
#define SM_SR  (SM_ZR + 2048)                 // 72704  float[4][128]
#define SM_CZ  (SM_SR + 2048)                 // 74752  float[2][128]
#define SM_CS  (SM_CZ + 1024)                 // 75776  float[2][128]
#define SM_TOTAL (SM_CS + 1024)               // 76800

// ---------------- tile worker (validated R8 core) --------------------------
__device__ __forceinline__ void do_tile(char* smem, int t) {
    __nv_bfloat16* sA = (__nv_bfloat16*)(smem + SM_A);
    __nv_bfloat16* sB = (__nv_bfloat16*)(smem + SM_B);
    int*   li = (int*)(smem + SM_LI);
    int*   lj = (int*)(smem + SM_LJ);
    float* zr = (float*)(smem + SM_ZR);
    float* sr = (float*)(smem + SM_SR);
    float* cz = (float*)(smem + SM_CZ);
    float* cs = (float*)(smem + SM_CS);

    // triangular pair decode: t = J(J+1)/2 + I, 0 <= I <= J < NT
    int J = (int)((sqrtf(8.0f * t + 1.0f) - 1.0f) * 0.5f);
    while ((J + 1) * (J + 2) / 2 <= t) ++J;
    while (J * (J + 1) / 2 > t) --J;
    int I = t - J * (J + 1) / 2;
    const bool offdiag = (I != J);

    const int tid  = threadIdx.x;
    const int wid  = tid >> 5, lane = tid & 31;
    const int ibase = I * TM, jbase = J * TN;

    // ---- load tiles ----
    {
        int r0 = tid >> 4, ch = tid & 15;
#pragma unroll
        for (int it = 0; it < 8; it++) {
            int r = r0 + it * 16;
            uint4 va = g_Q4[(size_t)(ibase + r) * (DK / 8) + ch];
            *(uint4*)((char*)sA + r * (LDA * 2) + ch * 16) = va;
            uint4 vb = g_Q4[(size_t)(jbase + r) * (DK / 8) + ch];
            *(uint4*)((char*)sB + r * (LDA * 2) + ch * 16) = vb;
        }
    }
    if (tid < TM) li[tid] = g_lbl[ibase + tid];
    else if (tid < TM + TN) lj[tid - TM] = g_lbl[jbase + tid - TM];
    __syncthreads();

    const int wy = wid >> 2, wx = wid & 3;
    const int m0w = wy * 64, n0w = wx * 32;
    const int g = lane >> 2, tq = lane & 3;

    float acc[4][4][4];
#pragma unroll
    for (int mt = 0; mt < 4; mt++)
#pragma unroll
        for (int nt = 0; nt < 4; nt++)
#pragma unroll
            for (int e = 0; e < 4; e++) acc[mt][nt][e] = 0.f;

#pragma unroll
    for (int ks = 0; ks < 8; ks++) {
        const int kk = ks * 16;
        uint32_t Af[4][4];
#pragma unroll
        for (int mt = 0; mt < 4; mt++) {
            const __nv_bfloat16* base = &sA[(m0w + mt * 16 + g) * LDA + kk + 2 * tq];
            Af[mt][0] = *(const uint32_t*)(base);
            Af[mt][1] = *(const uint32_t*)(base + 8 * LDA);
            Af[mt][2] = *(const uint32_t*)(base + 8);
            Af[mt][3] = *(const uint32_t*)(base + 8 * LDA + 8);
        }
        uint32_t Bf[4][2];
#pragma unroll
        for (int nt = 0; nt < 4; nt++) {
            const __nv_bfloat16* base = &sB[(n0w + nt * 8 + g) * LDA + kk + 2 * tq];
            Bf[nt][0] = *(const uint32_t*)(base);
            Bf[nt][1] = *(const uint32_t*)(base + 8);
        }
#pragma unroll
        for (int mt = 0; mt < 4; mt++)
#pragma unroll
            for (int nt = 0; nt < 4; nt++) {
                asm volatile(
                    "mma.sync.aligned.m16n8k16.row.col.f32.bf16.bf16.f32 "
                    "{%0,%1,%2,%3}, {%4,%5,%6,%7}, {%8,%9}, {%0,%1,%2,%3};"
                    : "+f"(acc[mt][nt][0]), "+f"(acc[mt][nt][1]),
                      "+f"(acc[mt][nt][2]), "+f"(acc[mt][nt][3])
                    : "r"(Af[mt][0]), "r"(Af[mt][1]),
                      "r"(Af[mt][2]), "r"(Af[mt][3]),
                      "r"(Bf[nt][0]), "r"(Bf[nt][1]));
            }
    }

    // ---- fused epilogue, specialized on diag/offdiag ----
    if (offdiag) {
        float zc[8], sc[8];
#pragma unroll
        for (int q = 0; q < 8; q++) { zc[q] = 0.f; sc[q] = 0.f; }
#pragma unroll
        for (int mt = 0; mt < 4; mt++) {
            int rl0 = m0w + mt * 16 + g;
            int rl1 = rl0 + 8;
            int l0 = li[rl0], l1 = li[rl1];
            float z0 = 0.f, s0 = 0.f, z1 = 0.f, s1 = 0.f;
#pragma unroll
            for (int nt = 0; nt < 4; nt++) {
                int cb = n0w + nt * 8 + 2 * tq;
#pragma unroll
                for (int e = 0; e < 2; e++) {
                    int col = cb + e, ljv = lj[col];
                    float lg0 = acc[mt][nt][e] * TAU_INV;
                    float lg1 = acc[mt][nt][2 + e] * TAU_INV;
                    float e0 = __expf(lg0);
                    float e1 = __expf(lg1);
                    float m0 = (ljv == l0) ? lg0 : 0.f;
                    float m1 = (ljv == l1) ? lg1 : 0.f;
                    z0 += e0; s0 += m0;
                    z1 += e1; s1 += m1;
                    zc[nt * 2 + e] += e0 + e1;
                    sc[nt * 2 + e] += m0 + m1;
                }
            }
#pragma unroll
            for (int m = 1; m <= 2; m <<= 1) {
                z0 += __shfl_xor_sync(0xffffffffu, z0, m);
                s0 += __shfl_xor_sync(0xffffffffu, s0, m);
                z1 += __shfl_xor_sync(0xffffffffu, z1, m);
                s1 += __shfl_xor_sync(0xffffffffu, s1, m);
            }
            if (tq == 0) {
                zr[wx * 128 + rl0] = z0;  sr[wx * 128 + rl0] = s0;
                zr[wx * 128 + rl1] = z1;  sr[wx * 128 + rl1] = s1;
            }
        }
#pragma unroll
        for (int m = 4; m <= 16; m <<= 1)
#pragma unroll
            for (int q = 0; q < 8; q++) {
                zc[q] += __shfl_xor_sync(0xffffffffu, zc[q], m);
                sc[q] += __shfl_xor_sync(0xffffffffu, sc[q], m);
            }
        if (g == 0) {
#pragma unroll
            for (int nt = 0; nt < 4; nt++)
#pragma unroll
                for (int e = 0; e < 2; e++) {
                    int col = n0w + nt * 8 + 2 * tq + e;
                    cz[wy * 128 + col] = zc[nt * 2 + e];
                    cs[wy * 128 + col] = sc[nt * 2 + e];
                }
        }
    } else {
#pragma unroll
        for (int mt = 0; mt < 4; mt++) {
            int rl0 = m0w + mt * 16 + g;
            int rl1 = rl0 + 8;
            int gi0 = ibase + rl0, gi1 = ibase + rl1;
            int l0 = li[rl0], l1 = li[rl1];
            float z0 = 0.f, s0 = 0.f, z1 = 0.f, s1 = 0.f;
#pragma unroll
            for (int nt = 0; nt < 4; nt++) {
                int cb = n0w + nt * 8 + 2 * tq;
#pragma unroll
                for (int e = 0; e < 2; e++) {
                    int col = cb + e, gj = jbase + col, ljv = lj[col];
                    float lg0 = acc[mt][nt][e] * TAU_INV;
                    float lg1 = acc[mt][nt][2 + e] * TAU_INV;
                    if (gi0 != gj) {
                        z0 += __expf(lg0);
                        if (ljv == l0) s0 += lg0;
                    }
                    if (gi1 != gj) {
                        z1 += __expf(lg1);
                        if (ljv == l1) s1 += lg1;
                    }
                }
            }
#pragma unroll
            for (int m = 1; m <= 2; m <<= 1) {
                z0 += __shfl_xor_sync(0xffffffffu, z0, m);
                s0 += __shfl_xor_sync(0xffffffffu, s0, m);
                z1 += __shfl_xor_sync(0xffffffffu, z1, m);
                s1 += __shfl_xor_sync(0xffffffffu, s1, m);
            }
            if (tq == 0) {
                zr[wx * 128 + rl0] = z0;  sr[wx * 128 + rl0] = s0;
                zr[wx * 128 + rl1] = z1;  sr[wx * 128 + rl1] = s1;
            }
        }
    }
    __syncthreads();

    if (tid < TM) {
        float Z = 0.f, S = 0.f;
#pragma unroll
        for (int w = 0; w < 4; w++) {
            Z += zr[w * 128 + tid];
            S += sr[w * 128 + tid];
        }
        g_Zp[(ibase + tid) * NT + J] = Z;
        g_Sp[(ibase + tid) * NT + J] = S;
        if (offdiag) {
            float Zc = cz[tid] + cz[128 + tid];
            float Sc = cs[tid] + cs[128 + tid];
            g_Zp[(jbase + tid) * NT + I] = Zc;
            g_Sp[(jbase + tid) * NT + I] = Sc;
        }
    }
}

// ---------------- the single persistent kernel -----------------------------
__global__ void __launch_bounds__(256, 2) fused_kernel(
    const float* __restrict__ zi, const float* __restrict__ zj,
    const long long* __restrict__ y, float* __restrict__ out) {
    extern __shared__ char smem[];
    const int tid = threadIdx.x, wid = tid >> 5, lane = tid & 31;
    const int bid = blockIdx.x;

    // ===== phase 1: normalize + bf16 convert + labels =====
    for (int row = bid * 8 + wid; row < N2; row += NCTA * 8) {
        const float* src = (row < NB) ? (zi + (size_t)row * DK)
                                      : (zj + (size_t)(row - NB) * DK);
        float4 v = ((const float4*)src)[lane];
        float ss = v.x * v.x + v.y * v.y + v.z * v.z + v.w * v.w;
#pragma unroll
        for (int m = 16; m; m >>= 1) ss += __shfl_xor_sync(0xffffffffu, ss, m);
        float inv = rsqrtf(fmaxf(ss, 1e-30f));
        uint32_t p01, p23;
        asm("cvt.rn.bf16x2.f32 %0, %1, %2;" : "=r"(p01)
            : "f"(v.y * inv), "f"(v.x * inv));
        asm("cvt.rn.bf16x2.f32 %0, %1, %2;" : "=r"(p23)
            : "f"(v.w * inv), "f"(v.z * inv));
        uint32_t* q32 = (uint32_t*)g_Q4;
        q32[row * 64 + 2 * lane + 0] = p01;
        q32[row * 64 + 2 * lane + 1] = p23;
        if (lane == 0) g_lbl[row] = (int)y[row & (NB - 1)];
    }
    grid_barrier();

    // ===== phase 1.5: CTA 0 builds label histogram (read after barrier 2) ==
    if (bid == 0) {
        __shared__ int hist[16];
        if (tid < 16) hist[tid] = 0;
        __syncthreads();
        int mycnt = 0;
#pragma unroll
        for (int it = 0; it < 16; it++) {
            int l = g_lbl[it * 256 + wid * 32 + lane];
#pragma unroll
            for (int b = 0; b < 10; b++) {
                unsigned m = __ballot_sync(0xffffffffu, l == b);
                if (lane == b) mycnt += __popc(m);
            }
        }
        if (lane < 10) atomicAdd(&hist[lane], mycnt);
        __syncthreads();
        if (tid < 16) g_hist[tid] = hist[tid];
    }

    // ===== phase 2: sim tiles (static assignment, deterministic) ===========
    do_tile(smem, bid);
    if (bid + NCTA < NPAIRS) {
        __syncthreads();
        do_tile(smem, bid + NCTA);
    }
    grid_barrier();

    // ===== phase 3: per-CTA finalize partials ==============================
    {
        __shared__ float red[256];
        float local = 0.f;
        int i = bid * 14 + tid;          // 14 rows per CTA, threads 0..13
        if (tid < 14 && i < N2) {
            const float4* zp4 = (const float4*)&g_Zp[i * NT];
            const float4* sp4 = (const float4*)&g_Sp[i * NT];
            float Z = 0.f, S = 0.f;
#pragma unroll
            for (int q = 0; q < 8; q++) {
                float4 a = zp4[q], b = sp4[q];
                Z += a.x + a.y + a.z + a.w;
                S += b.x + b.y + b.z + b.w;
            }
            float cnt = (float)(g_hist[g_lbl[i] & 15] - 1);
            local = S / cnt - logf(Z);
        }
        red[tid] = local;
        __syncthreads();
        for (int s = 128; s; s >>= 1) {
            if (tid < s) red[tid] += red[tid + s];
            __syncthreads();
        }
        if (tid == 0) g_part[bid] = red[0];
    }
    grid_barrier();

    // ===== phase 4: CTA 0 final reduction (fixed order) ====================
    if (bid == 0) {
        __shared__ float red[256];
        float v = (tid < NCTA) ? g_part[tid] : 0.f;
        if (tid + 256 < NCTA) v += g_part[tid + 256];
        red[tid] = v;
        __syncthreads();
        for (int s = 128; s; s >>= 1) {
            if (tid < s) red[tid] += red[tid + s];
            __syncthreads();
        }
        if (tid == 0) out[0] = -red[0] / (float)N2;
    }
}

// ---------------- launch ----------------
extern "C" void kernel_launch(void* const* d_in, const int* in_sizes, int n_in,
                              void* d_out, int out_size) {
    const float*     zi = (const float*)d_in[0];
    const float*     zj = (const float*)d_in[1];
    const long long* y  = (const long long*)d_in[2];
    float* out = (float*)d_out;

    cudaFuncSetAttribute(fused_kernel,
                         cudaFuncAttributeMaxDynamicSharedMemorySize, SM_TOTAL);

    fused_kernel<<<NCTA, 256, SM_TOTAL>>>(zi, zj, y, out);
}

// round 10
// speedup vs baseline: 1.1750x; 1.0115x over previous
#include <cuda_runtime.h>
#include <cuda_bf16.h>
#include <math.h>
#include <stdint.h>

#define N2 4096
#define NB 2048
#define DK 128
#define TAU_INV 10.0f
#define TM 128
#define TN 128
#define NT 32
#define NPAIRS (NT * (NT + 1) / 2)   // 528
#define LDA 136
#define NCTA 296                     // 148 SMs x 2 CTAs/SM

// ---------------- device scratch ----------------
__device__ uint4 g_Q4[(N2 * DK) / 8];
__device__ int   g_lbl[N2];
__device__ int   g_hist[16];
__device__ float g_Zp[N2 * NT];
__device__ float g_Sp[N2 * NT];
__device__ float g_part[NCTA];
__device__ int   g_bar;              // monotonic ticket barrier (never reset)
__device__ int   g_fin;              // monotonic finalize ticket

// ---------------- helpers ----------------
__device__ __forceinline__ uint32_t smem_u32(const void* p) {
    uint32_t a;
    asm("{ .reg .u64 t; cvta.to.shared.u64 t, %1; cvt.u32.u64 %0, t; }"
        : "=r"(a) : "l"(p));
    return a;
}
__device__ __forceinline__ void cp16(uint32_t saddr, const void* gaddr) {
    asm volatile("cp.async.cg.shared.global [%0], [%1], 16;"
                 :: "r"(saddr), "l"(gaddr) : "memory");
}
__device__ __forceinline__ void cp4(uint32_t saddr, const void* gaddr) {
    asm volatile("cp.async.ca.shared.global [%0], [%1], 4;"
                 :: "r"(saddr), "l"(gaddr) : "memory");
}
#define CP_COMMIT() asm volatile("cp.async.commit_group;" ::: "memory")
#define CP_WAIT0()  asm volatile("cp.async.wait_group 0;" ::: "memory")

__device__ __forceinline__ void grid_barrier() {
    __syncthreads();
    if (threadIdx.x == 0) {
        __threadfence();
        int t = atomicAdd(&g_bar, 1) + 1;
        int target = ((t + NCTA - 1) / NCTA) * NCTA;
        int v;
        do {
            asm volatile("ld.global.acquire.gpu.b32 %0, [%1];"
                         : "=r"(v) : "l"(&g_bar));
        } while (v < target);
    }
    __syncthreads();
}

// ---------------- smem layout ----------------
#define SM_A    0
#define SM_B    (TM * LDA * 2)                 // 34816
#define SM_LI   (SM_B + TN * LDA * 2)          // 69632
#define SM_LJ   (SM_LI + 512)                  // 70144
#define SM_ZR   (SM_LJ + 512)                  // 70656
#define SM_SR   (SM_ZR + 2048)                 // 72704
#define SM_CZ   (SM_SR + 2048)                 // 74752
#define SM_CS   (SM_CZ + 1024)                 // 75776
#define SM_LI2  (SM_CS + 1024)                 // 76800
#define SM_LJ2  (SM_LI2 + 512)                 // 77312
#define SM_TOTAL (SM_LJ2 + 512)                // 77824

__device__ __forceinline__ void decode_pair(int t, int& I, int& J) {
    int j = (int)((sqrtf(8.0f * t + 1.0f) - 1.0f) * 0.5f);
    while ((j + 1) * (j + 2) / 2 <= t) ++j;
    while (j * (j + 1) / 2 > t) --j;
    J = j; I = t - j * (j + 1) / 2;
}

// issue async loads for one tile pair (no waits; commit at end)
__device__ __forceinline__ void issue_tile_loads(uint32_t sbase, int I, int J,
                                                 int li_off, int lj_off) {
    int tid = threadIdx.x;
    int r0 = tid >> 4, ch = tid & 15;
#pragma unroll
    for (int it = 0; it < 8; it++) {
        int r = r0 + it * 16;
        cp16(sbase + SM_A + r * (LDA * 2) + ch * 16,
             &g_Q4[(size_t)(I * TM + r) * (DK / 8) + ch]);
        cp16(sbase + SM_B + r * (LDA * 2) + ch * 16,
             &g_Q4[(size_t)(J * TM + r) * (DK / 8) + ch]);
    }
    if (tid < TM) cp4(sbase + li_off + tid * 4, &g_lbl[I * TM + tid]);
    else if (tid < TM + TN)
        cp4(sbase + lj_off + (tid - TM) * 4, &g_lbl[J * TM + tid - TM]);
    CP_COMMIT();
}

// ---------------- mainloop: bf16 HMMA over K=128 ----------------
__device__ __forceinline__ void mma_tile(char* smem, float (&acc)[4][4][4]) {
    __nv_bfloat16* sA = (__nv_bfloat16*)(smem + SM_A);
    __nv_bfloat16* sB = (__nv_bfloat16*)(smem + SM_B);
    const int tid = threadIdx.x, wid = tid >> 5, lane = tid & 31;
    const int m0w = (wid >> 2) * 64, n0w = (wid & 3) * 32;
    const int g = lane >> 2, tq = lane & 3;

#pragma unroll
    for (int mt = 0; mt < 4; mt++)
#pragma unroll
        for (int nt = 0; nt < 4; nt++)
#pragma unroll
            for (int e = 0; e < 4; e++) acc[mt][nt][e] = 0.f;

#pragma unroll
    for (int ks = 0; ks < 8; ks++) {
        const int kk = ks * 16;
        uint32_t Af[4][4];
#pragma unroll
        for (int mt = 0; mt < 4; mt++) {
            const __nv_bfloat16* base = &sA[(m0w + mt * 16 + g) * LDA + kk + 2 * tq];
            Af[mt][0] = *(const uint32_t*)(base);
            Af[mt][1] = *(const uint32_t*)(base + 8 * LDA);
            Af[mt][2] = *(const uint32_t*)(base + 8);
            Af[mt][3] = *(const uint32_t*)(base + 8 * LDA + 8);
        }
        uint32_t Bf[4][2];
#pragma unroll
        for (int nt = 0; nt < 4; nt++) {
            const __nv_bfloat16* base = &sB[(n0w + nt * 8 + g) * LDA + kk + 2 * tq];
            Bf[nt][0] = *(const uint32_t*)(base);
            Bf[nt][1] = *(const uint32_t*)(base + 8);
        }
#pragma unroll
        for (int mt = 0; mt < 4; mt++)
#pragma unroll
            for (int nt = 0; nt < 4; nt++) {
                asm volatile(
                    "mma.sync.aligned.m16n8k16.row.col.f32.bf16.bf16.f32 "
                    "{%0,%1,%2,%3}, {%4,%5,%6,%7}, {%8,%9}, {%0,%1,%2,%3};"
                    : "+f"(acc[mt][nt][0]), "+f"(acc[mt][nt][1]),
                      "+f"(acc[mt][nt][2]), "+f"(acc[mt][nt][3])
                    : "r"(Af[mt][0]), "r"(Af[mt][1]),
                      "r"(Af[mt][2]), "r"(Af[mt][3]),
                      "r"(Bf[nt][0]), "r"(Bf[nt][1]));
            }
    }
}

// ---------------- epilogue: exp + masked sums into zr/sr/cz/cs -------------
__device__ __forceinline__ void epilogue(char* smem, int I, int J,
                                         float (&acc)[4][4][4],
                                         int li_off, int lj_off) {
    int*   li = (int*)(smem + li_off);
    int*   lj = (int*)(smem + lj_off);
    float* zr = (float*)(smem + SM_ZR);
    float* sr = (float*)(smem + SM_SR);
    float* cz = (float*)(smem + SM_CZ);
    float* cs = (float*)(smem + SM_CS);
    const int tid = threadIdx.x, wid = tid >> 5, lane = tid & 31;
    const int wy = wid >> 2, wx = wid & 3;
    const int m0w = wy * 64, n0w = wx * 32;
    const int g = lane >> 2, tq = lane & 3;
    const bool offdiag = (I != J);
    const int ibase = I * TM, jbase = J * TN;

    if (offdiag) {
        float zc[8], sc[8];
#pragma unroll
        for (int q = 0; q < 8; q++) { zc[q] = 0.f; sc[q] = 0.f; }
#pragma unroll
        for (int mt = 0; mt < 4; mt++) {
            int rl0 = m0w + mt * 16 + g, rl1 = rl0 + 8;
            int l0 = li[rl0], l1 = li[rl1];
            float z0 = 0.f, s0 = 0.f, z1 = 0.f, s1 = 0.f;
#pragma unroll
            for (int nt = 0; nt < 4; nt++) {
                int cb = n0w + nt * 8 + 2 * tq;
#pragma unroll
                for (int e = 0; e < 2; e++) {
                    int col = cb + e, ljv = lj[col];
                    float lg0 = acc[mt][nt][e] * TAU_INV;
                    float lg1 = acc[mt][nt][2 + e] * TAU_INV;
                    float e0 = __expf(lg0), e1 = __expf(lg1);
                    float m0 = (ljv == l0) ? lg0 : 0.f;
                    float m1 = (ljv == l1) ? lg1 : 0.f;
                    z0 += e0; s0 += m0;
                    z1 += e1; s1 += m1;
                    zc[nt * 2 + e] += e0 + e1;
                    sc[nt * 2 + e] += m0 + m1;
                }
            }
#pragma unroll
            for (int m = 1; m <= 2; m <<= 1) {
                z0 += __shfl_xor_sync(0xffffffffu, z0, m);
                s0 += __shfl_xor_sync(0xffffffffu, s0, m);
                z1 += __shfl_xor_sync(0xffffffffu, z1, m);
                s1 += __shfl_xor_sync(0xffffffffu, s1, m);
            }
            if (tq == 0) {
                zr[wx * 128 + rl0] = z0;  sr[wx * 128 + rl0] = s0;
                zr[wx * 128 + rl1] = z1;  sr[wx * 128 + rl1] = s1;
            }
        }
#pragma unroll
        for (int m = 4; m <= 16; m <<= 1)
#pragma unroll
            for (int q = 0; q < 8; q++) {
                zc[q] += __shfl_xor_sync(0xffffffffu, zc[q], m);
                sc[q] += __shfl_xor_sync(0xffffffffu, sc[q], m);
            }
        if (g == 0) {
#pragma unroll
            for (int nt = 0; nt < 4; nt++)
#pragma unroll
                for (int e = 0; e < 2; e++) {
                    int col = n0w + nt * 8 + 2 * tq + e;
                    cz[wy * 128 + col] = zc[nt * 2 + e];
                    cs[wy * 128 + col] = sc[nt * 2 + e];
                }
        }
    } else {
#pragma unroll
        for (int mt = 0; mt < 4; mt++) {
            int rl0 = m0w + mt * 16 + g, rl1 = rl0 + 8;
            int gi0 = ibase + rl0, gi1 = ibase + rl1;
            int l0 = li[rl0], l1 = li[rl1];
            float z0 = 0.f, s0 = 0.f, z1 = 0.f, s1 = 0.f;
#pragma unroll
            for (int nt = 0; nt < 4; nt++) {
                int cb = n0w + nt * 8 + 2 * tq;
#pragma unroll
                for (int e = 0; e < 2; e++) {
                    int col = cb + e, gj = jbase + col, ljv = lj[col];
                    float lg0 = acc[mt][nt][e] * TAU_INV;
                    float lg1 = acc[mt][nt][2 + e] * TAU_INV;
                    if (gi0 != gj) {
                        z0 += __expf(lg0);
                        if (ljv == l0) s0 += lg0;
                    }
                    if (gi1 != gj) {
                        z1 += __expf(lg1);
                        if (ljv == l1) s1 += lg1;
                    }
                }
            }
#pragma unroll
            for (int m = 1; m <= 2; m <<= 1) {
                z0 += __shfl_xor_sync(0xffffffffu, z0, m);
                s0 += __shfl_xor_sync(0xffffffffu, s0, m);
                z1 += __shfl_xor_sync(0xffffffffu, z1, m);
                s1 += __shfl_xor_sync(0xffffffffu, s1, m);
            }
            if (tq == 0) {
                zr[wx * 128 + rl0] = z0;  sr[wx * 128 + rl0] = s0;
                zr[wx * 128 + rl1] = z1;  sr[wx * 128 + rl1] = s1;
            }
        }
    }
}

// ---------------- final per-tile global writes -----------------------------
__device__ __forceinline__ void finwr(char* smem, int I, int J) {
    float* zr = (float*)(smem + SM_ZR);
    float* sr = (float*)(smem + SM_SR);
    float* cz = (float*)(smem + SM_CZ);
    float* cs = (float*)(smem + SM_CS);
    const int tid = threadIdx.x;
    if (tid < TM) {
        float Z = 0.f, S = 0.f;
#pragma unroll
        for (int w = 0; w < 4; w++) {
            Z += zr[w * 128 + tid];
            S += sr[w * 128 + tid];
        }
        g_Zp[(I * TM + tid) * NT + J] = Z;
        g_Sp[(I * TM + tid) * NT + J] = S;
        if (I != J) {
            g_Zp[(J * TM + tid) * NT + I] = cz[tid] + cz[128 + tid];
            g_Sp[(J * TM + tid) * NT + I] = cs[tid] + cs[128 + tid];
        }
    }
}

// ---------------- the single persistent kernel -----------------------------
__global__ void __launch_bounds__(256, 2) fused_kernel(
    const float* __restrict__ zi, const float* __restrict__ zj,
    const long long* __restrict__ y, float* __restrict__ out) {
    extern __shared__ char smem[];
    const uint32_t sbase = smem_u32(smem);
    const int tid = threadIdx.x, wid = tid >> 5, lane = tid & 31;
    const int bid = blockIdx.x;

    // ===== phase 1: normalize + bf16 convert + labels =====
    for (int row = bid * 8 + wid; row < N2; row += NCTA * 8) {
        const float* src = (row < NB) ? (zi + (size_t)row * DK)
                                      : (zj + (size_t)(row - NB) * DK);
        float4 v = ((const float4*)src)[lane];
        float ss = v.x * v.x + v.y * v.y + v.z * v.z + v.w * v.w;
#pragma unroll
        for (int m = 16; m; m >>= 1) ss += __shfl_xor_sync(0xffffffffu, ss, m);
        float inv = rsqrtf(fmaxf(ss, 1e-30f));
        uint32_t p01, p23;
        asm("cvt.rn.bf16x2.f32 %0, %1, %2;" : "=r"(p01)
            : "f"(v.y * inv), "f"(v.x * inv));
        asm("cvt.rn.bf16x2.f32 %0, %1, %2;" : "=r"(p23)
            : "f"(v.w * inv), "f"(v.z * inv));
        uint32_t* q32 = (uint32_t*)g_Q4;
        q32[row * 64 + 2 * lane + 0] = p01;
        q32[row * 64 + 2 * lane + 1] = p23;
        if (lane == 0) g_lbl[row] = (int)y[row & (NB - 1)];
    }
    grid_barrier();

    // ===== phase 1.5: CTA 0 builds label histogram =====
    if (bid == 0) {
        __shared__ int hist[16];
        if (tid < 16) hist[tid] = 0;
        __syncthreads();
        int mycnt = 0;
#pragma unroll
        for (int it = 0; it < 16; it++) {
            int l = g_lbl[it * 256 + wid * 32 + lane];
#pragma unroll
            for (int b = 0; b < 10; b++) {
                unsigned m = __ballot_sync(0xffffffffu, l == b);
                if (lane == b) mycnt += __popc(m);
            }
        }
        if (lane < 10) atomicAdd(&hist[lane], mycnt);
        __syncthreads();
        if (tid < 16) g_hist[tid] = hist[tid];
    }

    // ===== phase 2: sim tiles, cp.async-prefetched pipeline ================
    {
        int I0, J0, I1 = 0, J1 = 0;
        decode_pair(bid, I0, J0);
        const bool has1 = (bid + NCTA < NPAIRS);
        if (has1) decode_pair(bid + NCTA, I1, J1);

        float acc[4][4][4];
        issue_tile_loads(sbase, I0, J0, SM_LI, SM_LJ);
        CP_WAIT0();
        __syncthreads();
        mma_tile(smem, acc);
        __syncthreads();                                   // sA/sB reads done
        if (has1) issue_tile_loads(sbase, I1, J1, SM_LI2, SM_LJ2);  // async
        epilogue(smem, I0, J0, acc, SM_LI, SM_LJ);          // exp overlaps cp
        CP_WAIT0();
        __syncthreads();                                   // zr/sr + tile2 ready
        finwr(smem, I0, J0);
        if (has1) {
            mma_tile(smem, acc);
            __syncthreads();
            epilogue(smem, I1, J1, acc, SM_LI2, SM_LJ2);
            __syncthreads();
            finwr(smem, I1, J1);
        }
    }
    grid_barrier();

    // ===== phase 3: per-CTA partials; last ticket does the final reduce ====
    {
        __shared__ float red[256];
        __shared__ int amLast;
        float local = 0.f;
        int i = bid * 14 + tid;           // 14 rows per CTA
        if (tid < 14 && i < N2) {
            const float4* zp4 = (const float4*)&g_Zp[i * NT];
            const float4* sp4 = (const float4*)&g_Sp[i * NT];
            float Z = 0.f, S = 0.f;
#pragma unroll
            for (int q = 0; q < 8; q++) {
                float4 a = zp4[q], b = sp4[q];
                Z += a.x + a.y + a.z + a.w;
                S += b.x + b.y + b.z + b.w;
            }
            float cnt = (float)(g_hist[g_lbl[i] & 15] - 1);
            local = S / cnt - logf(Z);
        }
        red[tid] = local;
        __syncthreads();
        for (int s = 128; s; s >>= 1) {
            if (tid < s) red[tid] += red[tid + s];
            __syncthreads();
        }
        if (tid == 0) {
            g_part[bid] = red[0];
            __threadfence();
            int t = atomicAdd(&g_fin, 1);
            amLast = (((t + 1) % NCTA) == 0);
        }
        __syncthreads();
        if (amLast) {
            float v = (tid < NCTA) ? __ldcg(&g_part[tid]) : 0.f;
            if (tid + 256 < NCTA) v += __ldcg(&g_part[tid + 256]);
            red[tid] = v;
            __syncthreads();
            for (int s = 128; s; s >>= 1) {
                if (tid < s) red[tid] += red[tid + s];
                __syncthreads();
            }
            if (tid == 0) out[0] = -red[0] / (float)N2;
        }
    }
}

// ---------------- launch ----------------
extern "C" void kernel_launch(void* const* d_in, const int* in_sizes, int n_in,
                              void* d_out, int out_size) {
    const float*     zi = (const float*)d_in[0];
    const float*     zj = (const float*)d_in[1];
    const long long* y  = (const long long*)d_in[2];
    float* out = (float*)d_out;

    cudaFuncSetAttribute(fused_kernel,
                         cudaFuncAttributeMaxDynamicSharedMemorySize, SM_TOTAL);

    fused_kernel<<<NCTA, 256, SM_TOTAL>>>(zi, zj, y, out);
}